// round 10
// baseline (speedup 1.0000x reference)
#include <cuda_runtime.h>
#include <cuda_bf16.h>
#include <cstdint>

// Problem constants (from reference):
//   R_MAX=32, S_MAX=2 -> C_R = 66, C_S = 6, DIM_PAIR = 128
//   W rows: [0,66) = W_si, [66,132) = W_ti, 132 = w_ent, [133,139) = W_sym
#define DIM   128
#define NCTA  296    // best-measured grid; 152-SM GB300, 2 CTAs/SM

__global__ __launch_bounds__(1024, 2)
void rpe_kernel(const int* __restrict__ seq_index,
                const int* __restrict__ seq_color,
                const int* __restrict__ seq_sym,
                const int* __restrict__ seq_entity,
                const int* __restrict__ token_index,
                const float* __restrict__ W,
                float* __restrict__ out,
                int L)
{
    // Tables (folded):
    //   sT1[d]  = W_si[d] + W_ti[65]      (66 rows) — d_ti==65 fast path folded in
    //   sSym[d] = W_sym[d] + (d!=5)*w_ent (6 rows)  — bij_entity <=> d_sym!=5
    //   skey[j] = color | entity<<2 | sym<<4 | seq_index<<6 | token_index<<16
    __shared__ float    sT1[66 * DIM];
    __shared__ float    sSym[6 * DIM];
    __shared__ unsigned skey[1024];

    const int tid = threadIdx.x;

    {
        const float4* W4 = reinterpret_cast<const float4*>(W);
        float4*       T4 = reinterpret_cast<float4*>(sT1);
        for (int idx = tid; idx < 66 * (DIM / 4); idx += blockDim.x) {
            int k4 = idx & (DIM / 4 - 1);
            float4 a = __ldg(W4 + idx);                       // W_si[d]
            float4 b = __ldg(W4 + 131 * (DIM / 4) + k4);      // W_ti[65]
            T4[idx] = make_float4(a.x + b.x, a.y + b.y, a.z + b.z, a.w + b.w);
        }
        float4* S4 = reinterpret_cast<float4*>(sSym);
        for (int idx = tid; idx < 6 * (DIM / 4); idx += blockDim.x) {
            int d  = idx / (DIM / 4);
            int k4 = idx & (DIM / 4 - 1);
            float4 a = __ldg(W4 + (133 + d) * (DIM / 4) + k4);
            if (d != 5) {
                float4 e = __ldg(W4 + 132 * (DIM / 4) + k4);  // w_ent
                a = make_float4(a.x + e.x, a.y + e.y, a.z + e.z, a.w + e.w);
            }
            S4[idx] = a;
        }
    }
    for (int j = tid; j < L; j += blockDim.x) {
        unsigned c  = (unsigned)__ldg(seq_color  + j) & 3u;
        unsigned e  = (unsigned)__ldg(seq_entity + j) & 3u;
        unsigned s  = (unsigned)__ldg(seq_sym    + j) & 3u;
        unsigned si = (unsigned)__ldg(seq_index  + j) & 0x3FFu;
        unsigned ti = (unsigned)__ldg(token_index + j) & 0x3FFu;
        skey[j] = c | (e << 2) | (s << 4) | (si << 6) | (ti << 16);
    }
    __syncthreads();

    const int lane = tid & 31;
    const int warp = tid >> 5;

    // i-independent hot rows in registers:
    const float4 base = *reinterpret_cast<const float4*>(sT1  + 65 * DIM + lane * 4);
    const float4 sym5 = *reinterpret_cast<const float4*>(sSym + 5 * DIM  + lane * 4);
    const float4 hot  = make_float4(base.x + sym5.x, base.y + sym5.y,
                                    base.z + sym5.z, base.w + sym5.w);

    // TWO adjacent pairs per warp per step (j even, j+1): one ki decode, two
    // independent STG.128.cs back-to-back (store MLP), loop overhead halved.
    // Consecutive warps still cover consecutive pair-couples -> chip-wide
    // instantaneous write window stays contiguous (~9.7 MB).
    const int npairs      = L * L;                        // 2^20
    const int total_warps = gridDim.x * (blockDim.x >> 5);   // 9472
    const int gwarp       = blockIdx.x * (blockDim.x >> 5) + warp;

    const int pstep  = 2 * total_warps;                   // 18944
    const int step_i = pstep / L;                         // 18
    const int step_j = pstep - step_i * L;                // 512

    int p = 2 * gwarp;                                    // even pair base
    int i = p / L;                                        // once
    int j = p - i * L;                                    // even (L even)

    float4* __restrict__ dst =
        reinterpret_cast<float4*>(out) + (size_t)p * (DIM / 4) + lane;
    const int dst_step = pstep * (DIM / 4);

    while (p < npairs) {
        const unsigned ki  = skey[i];
        const unsigned kj0 = skey[j];
        const unsigned kj1 = skey[j + 1];        // j even, j+1 < L: same row i
        const unsigned x0  = ki ^ kj0;
        const unsigned x1  = ki ^ kj1;

        const int si_i = (int)((ki >> 6)  & 0x3FFu);
        const int ss_i = (int)((ki >> 4)  & 3u);

        float4 v0, v1;

        // ---- pair 0 ----
        if ((x0 & 3u) && (x0 & 12u)) {
            v0 = hot;
        } else {
            if (!(x0 & 3u)) {
                const int sij = (int)((kj0 >> 6) & 0x3FFu);
                int d = min(max(si_i - sij, -32), 32) + 32;
                v0 = *reinterpret_cast<const float4*>(sT1 + d * DIM + lane * 4);
                if (si_i == sij) {
                    const int ti_i = (int)((ki  >> 16) & 0x3FFu);
                    const int tij  = (int)((kj0 >> 16) & 0x3FFu);
                    int dt = min(max(ti_i - tij, -32), 32) + 32;
                    float4 wt  = __ldg(reinterpret_cast<const float4*>(W + (66 + dt) * DIM + lane * 4));
                    float4 w65 = __ldg(reinterpret_cast<const float4*>(W + 131 * DIM       + lane * 4));
                    v0.x += wt.x - w65.x; v0.y += wt.y - w65.y;
                    v0.z += wt.z - w65.z; v0.w += wt.w - w65.w;
                }
            } else {
                v0 = base;
            }
            float4 s;
            if (!(x0 & 12u)) {
                const int ssj = (int)((kj0 >> 4) & 3u);
                int ds = min(max(ss_i - ssj, -2), 2) + 2;
                s = *reinterpret_cast<const float4*>(sSym + ds * DIM + lane * 4);
            } else {
                s = sym5;
            }
            v0.x += s.x; v0.y += s.y; v0.z += s.z; v0.w += s.w;
        }

        // ---- pair 1 ----
        if ((x1 & 3u) && (x1 & 12u)) {
            v1 = hot;
        } else {
            if (!(x1 & 3u)) {
                const int sij = (int)((kj1 >> 6) & 0x3FFu);
                int d = min(max(si_i - sij, -32), 32) + 32;
                v1 = *reinterpret_cast<const float4*>(sT1 + d * DIM + lane * 4);
                if (si_i == sij) {
                    const int ti_i = (int)((ki  >> 16) & 0x3FFu);
                    const int tij  = (int)((kj1 >> 16) & 0x3FFu);
                    int dt = min(max(ti_i - tij, -32), 32) + 32;
                    float4 wt  = __ldg(reinterpret_cast<const float4*>(W + (66 + dt) * DIM + lane * 4));
                    float4 w65 = __ldg(reinterpret_cast<const float4*>(W + 131 * DIM       + lane * 4));
                    v1.x += wt.x - w65.x; v1.y += wt.y - w65.y;
                    v1.z += wt.z - w65.z; v1.w += wt.w - w65.w;
                }
            } else {
                v1 = base;
            }
            float4 s;
            if (!(x1 & 12u)) {
                const int ssj = (int)((kj1 >> 4) & 3u);
                int ds = min(max(ss_i - ssj, -2), 2) + 2;
                s = *reinterpret_cast<const float4*>(sSym + ds * DIM + lane * 4);
            } else {
                s = sym5;
            }
            v1.x += s.x; v1.y += s.y; v1.z += s.z; v1.w += s.w;
        }

        // two independent streaming stores, back-to-back (store MLP)
        __stcs(dst,            v0);
        __stcs(dst + DIM / 4,  v1);

        // advance one grid-stride step — branch-free 32-bit index update
        p   += pstep;
        dst += dst_step;
        j   += step_j;
        int wrap = (j >= L);
        i   += step_i + wrap;
        j   -= wrap ? L : 0;
    }
}

extern "C" void kernel_launch(void* const* d_in, const int* in_sizes, int n_in,
                              void* d_out, int out_size)
{
    const int* seq_index   = (const int*)d_in[0];
    const int* seq_color   = (const int*)d_in[1];
    const int* seq_sym     = (const int*)d_in[2];
    const int* seq_entity  = (const int*)d_in[3];
    const int* token_index = (const int*)d_in[4];
    const float* W         = (const float*)d_in[5];
    float* out             = (float*)d_out;

    const int L = in_sizes[0];   // 1024 (B=1)

    rpe_kernel<<<NCTA, 1024>>>(seq_index, seq_color, seq_sym, seq_entity,
                               token_index, W, out, L);
}

// round 11
// speedup vs baseline: 1.3861x; 1.3861x over previous
#include <cuda_runtime.h>
#include <cuda_bf16.h>
#include <cstdint>

// Problem constants (from reference):
//   R_MAX=32, S_MAX=2 -> C_R = 66, C_S = 6, DIM_PAIR = 128
//   W rows: [0,66) = W_si, [66,132) = W_ti, 132 = w_ent, [133,139) = W_sym
//
// Session-established optimum (rounds 1-10 evidence):
//   * one pair per warp per step, warp-interleaved pair order
//     (keeps chip-wide instantaneous write window ~4.8MB contiguous;
//      2x/16x wider windows regressed 25-50%)
//   * STG.128 + .cs  (.wb -10us, .wt -10us, 256-bit -35..47us)
//   * grid 296 x 1024, 2 CTAs/SM
//   -> 90.2us, DRAM 67%, ~5.95 TB/s effective write BW (HBM write ceiling)
#define DIM 128
#define NCTA 296

__global__ __launch_bounds__(1024, 2)
void rpe_kernel(const int* __restrict__ seq_index,
                const int* __restrict__ seq_color,
                const int* __restrict__ seq_sym,
                const int* __restrict__ seq_entity,
                const int* __restrict__ token_index,
                const float* __restrict__ W,
                float* __restrict__ out,
                int L)
{
    // Shared tables:
    //   T1[d][k]   = W_si[d][k] + W_ti[65][k]      (66 rows) — d_ti==65 fast path folded
    //   Wsym[d][k] = W_sym[d][k] + (d!=5)*w_ent[k] (6 rows)  — bij_entity <=> d_sym!=5
    __shared__ float sT1[66 * DIM];
    __shared__ float sSym[6 * DIM];

    const int tid = threadIdx.x;

    for (int idx = tid; idx < 66 * DIM; idx += blockDim.x) {
        int k = idx & (DIM - 1);
        sT1[idx] = W[idx] + W[131 * DIM + k];
    }
    for (int idx = tid; idx < 6 * DIM; idx += blockDim.x) {
        int d = idx >> 7, k = idx & (DIM - 1);
        float v = W[(133 + d) * DIM + k];
        if (d != 5) v += W[132 * DIM + k];
        sSym[idx] = v;
    }
    __syncthreads();

    const int lane = tid & 31;
    const int warp = tid >> 5;

    // Register-cached hot rows (i-independent):
    const float4 base = *reinterpret_cast<const float4*>(sT1  + 65 * DIM + lane * 4);
    const float4 sym5 = *reinterpret_cast<const float4*>(sSym + 5 * DIM  + lane * 4);
    const float4 hot  = make_float4(base.x + sym5.x, base.y + sym5.y,
                                    base.z + sym5.z, base.w + sym5.w);

    // Persistent warps grid-stride over the flattened pair space.
    const long long npairs      = (long long)L * (long long)L;
    const int       total_warps = gridDim.x * (blockDim.x >> 5);
    const int       gwarp       = blockIdx.x * (blockDim.x >> 5) + warp;

    float4* __restrict__ out4 = reinterpret_cast<float4*>(out);

    for (long long p = gwarp; p < npairs; p += total_warps) {
        const int i = (int)(p / L);
        const int j = (int)(p - (long long)i * L);

        const int sc_i = __ldg(seq_color  + i);
        const int se_i = __ldg(seq_entity + i);
        const int scj  = __ldg(seq_color  + j);
        const int sej  = __ldg(seq_entity + j);
        const bool bc = (sc_i == scj);
        const bool be = (se_i == sej);

        float4 v;
        if (!bc && !be) {
            v = hot;                                   // ~56% of pairs: zero table reads
        } else {
            if (bc) {
                const int si_i = __ldg(seq_index + i);
                const int sij  = __ldg(seq_index + j);
                int d = min(max(si_i - sij, -32), 32) + 32;
                v = *reinterpret_cast<const float4*>(sT1 + d * DIM + lane * 4);
                if (si_i == sij) {
                    // very rare (~0.1%): real token-index bin; add W_ti[d_ti]-W_ti[65] from gmem
                    const int ti_i = __ldg(token_index + i);
                    const int tij  = __ldg(token_index + j);
                    int dt = min(max(ti_i - tij, -32), 32) + 32;
                    float4 wt  = __ldg(reinterpret_cast<const float4*>(W + (66 + dt) * DIM + lane * 4));
                    float4 w65 = __ldg(reinterpret_cast<const float4*>(W + 131 * DIM       + lane * 4));
                    v.x += wt.x - w65.x; v.y += wt.y - w65.y;
                    v.z += wt.z - w65.z; v.w += wt.w - w65.w;
                }
            } else {
                v = base;
            }
            float4 s;
            if (be) {
                const int ss_i = __ldg(seq_sym + i);
                const int ssj  = __ldg(seq_sym + j);
                int ds = min(max(ss_i - ssj, -2), 2) + 2;
                s = *reinterpret_cast<const float4*>(sSym + ds * DIM + lane * 4);
            } else {
                s = sym5;
            }
            v.x += s.x; v.y += s.y; v.z += s.z; v.w += s.w;
        }

        // streaming store: output is write-once, never re-read -> don't pollute L2
        __stcs(out4 + p * (DIM / 4) + lane, v);
    }
}

extern "C" void kernel_launch(void* const* d_in, const int* in_sizes, int n_in,
                              void* d_out, int out_size)
{
    const int* seq_index   = (const int*)d_in[0];
    const int* seq_color   = (const int*)d_in[1];
    const int* seq_sym     = (const int*)d_in[2];
    const int* seq_entity  = (const int*)d_in[3];
    const int* token_index = (const int*)d_in[4];
    const float* W         = (const float*)d_in[5];
    float* out             = (float*)d_out;

    const int L = in_sizes[0];   // 1024 (B=1)

    rpe_kernel<<<NCTA, 1024>>>(seq_index, seq_color, seq_sym, seq_entity,
                               token_index, W, out, L);
}

// round 12
// speedup vs baseline: 1.4111x; 1.0181x over previous
#include <cuda_runtime.h>
#include <cuda_bf16.h>
#include <cstdint>

// Problem constants (from reference):
//   R_MAX=32, S_MAX=2 -> C_R = 66, C_S = 6, DIM_PAIR = 128
//   W rows: [0,66) = W_si, [66,132) = W_ti, 132 = w_ent, [133,139) = W_sym
//
// Session-established optimum (rounds 1-11 evidence):
//   * one pair per warp per step, warp-interleaved pair order
//     (chip-wide instantaneous write window ~4.8MB contiguous;
//      2x/16x wider windows regressed 25-50%)
//   * STG.128 + .cs  (.wb -10us, .wt -10us, 256-bit -35..47us)
//   * champion body reproduced at 90.18us twice (R2, R11)
// This round: SINGLE change 296 -> 304 CTAs (use all 152 SMs; R7 proved
// 304 run concurrently). Only untested cell of the config matrix.
#define DIM 128
#define NCTA 304

__global__ __launch_bounds__(1024, 2)
void rpe_kernel(const int* __restrict__ seq_index,
                const int* __restrict__ seq_color,
                const int* __restrict__ seq_sym,
                const int* __restrict__ seq_entity,
                const int* __restrict__ token_index,
                const float* __restrict__ W,
                float* __restrict__ out,
                int L)
{
    // Shared tables:
    //   T1[d][k]   = W_si[d][k] + W_ti[65][k]      (66 rows) — d_ti==65 fast path folded
    //   Wsym[d][k] = W_sym[d][k] + (d!=5)*w_ent[k] (6 rows)  — bij_entity <=> d_sym!=5
    __shared__ float sT1[66 * DIM];
    __shared__ float sSym[6 * DIM];

    const int tid = threadIdx.x;

    for (int idx = tid; idx < 66 * DIM; idx += blockDim.x) {
        int k = idx & (DIM - 1);
        sT1[idx] = W[idx] + W[131 * DIM + k];
    }
    for (int idx = tid; idx < 6 * DIM; idx += blockDim.x) {
        int d = idx >> 7, k = idx & (DIM - 1);
        float v = W[(133 + d) * DIM + k];
        if (d != 5) v += W[132 * DIM + k];
        sSym[idx] = v;
    }
    __syncthreads();

    const int lane = tid & 31;
    const int warp = tid >> 5;

    // Register-cached hot rows (i-independent):
    const float4 base = *reinterpret_cast<const float4*>(sT1  + 65 * DIM + lane * 4);
    const float4 sym5 = *reinterpret_cast<const float4*>(sSym + 5 * DIM  + lane * 4);
    const float4 hot  = make_float4(base.x + sym5.x, base.y + sym5.y,
                                    base.z + sym5.z, base.w + sym5.w);

    // Persistent warps grid-stride over the flattened pair space.
    const long long npairs      = (long long)L * (long long)L;
    const int       total_warps = gridDim.x * (blockDim.x >> 5);
    const int       gwarp       = blockIdx.x * (blockDim.x >> 5) + warp;

    float4* __restrict__ out4 = reinterpret_cast<float4*>(out);

    for (long long p = gwarp; p < npairs; p += total_warps) {
        const int i = (int)(p / L);
        const int j = (int)(p - (long long)i * L);

        const int sc_i = __ldg(seq_color  + i);
        const int se_i = __ldg(seq_entity + i);
        const int scj  = __ldg(seq_color  + j);
        const int sej  = __ldg(seq_entity + j);
        const bool bc = (sc_i == scj);
        const bool be = (se_i == sej);

        float4 v;
        if (!bc && !be) {
            v = hot;                                   // ~56% of pairs: zero table reads
        } else {
            if (bc) {
                const int si_i = __ldg(seq_index + i);
                const int sij  = __ldg(seq_index + j);
                int d = min(max(si_i - sij, -32), 32) + 32;
                v = *reinterpret_cast<const float4*>(sT1 + d * DIM + lane * 4);
                if (si_i == sij) {
                    // very rare (~0.1%): real token-index bin; add W_ti[d_ti]-W_ti[65] from gmem
                    const int ti_i = __ldg(token_index + i);
                    const int tij  = __ldg(token_index + j);
                    int dt = min(max(ti_i - tij, -32), 32) + 32;
                    float4 wt  = __ldg(reinterpret_cast<const float4*>(W + (66 + dt) * DIM + lane * 4));
                    float4 w65 = __ldg(reinterpret_cast<const float4*>(W + 131 * DIM       + lane * 4));
                    v.x += wt.x - w65.x; v.y += wt.y - w65.y;
                    v.z += wt.z - w65.z; v.w += wt.w - w65.w;
                }
            } else {
                v = base;
            }
            float4 s;
            if (be) {
                const int ss_i = __ldg(seq_sym + i);
                const int ssj  = __ldg(seq_sym + j);
                int ds = min(max(ss_i - ssj, -2), 2) + 2;
                s = *reinterpret_cast<const float4*>(sSym + ds * DIM + lane * 4);
            } else {
                s = sym5;
            }
            v.x += s.x; v.y += s.y; v.z += s.z; v.w += s.w;
        }

        // streaming store: output is write-once, never re-read -> don't pollute L2
        __stcs(out4 + p * (DIM / 4) + lane, v);
    }
}

extern "C" void kernel_launch(void* const* d_in, const int* in_sizes, int n_in,
                              void* d_out, int out_size)
{
    const int* seq_index   = (const int*)d_in[0];
    const int* seq_color   = (const int*)d_in[1];
    const int* seq_sym     = (const int*)d_in[2];
    const int* seq_entity  = (const int*)d_in[3];
    const int* token_index = (const int*)d_in[4];
    const float* W         = (const float*)d_in[5];
    float* out             = (float*)d_out;

    const int L = in_sizes[0];   // 1024 (B=1)

    rpe_kernel<<<NCTA, 1024>>>(seq_index, seq_color, seq_sym, seq_entity,
                               token_index, W, out, L);
}